// round 10
// baseline (speedup 1.0000x reference)
#include <cuda_runtime.h>

// SheafLoss: B=4 T=1024 P=16 D=64 R=32 K=64, TAU=1
// d_in[0]=m (B,T,P,D) f32, d_in[1]=w (B,T,P) f32,
// d_in[2]=p (B,T,P,K) f32, d_in[3]=patch_centers (R,D) f32
// out: scalar f32

#define BT    4096
#define P_    16
#define D_    64
#define R_    32
#define K_    64
#define TPC   2
#define LN2   0.6931471805599453f

__device__ double g_acc;
__device__ unsigned int g_done;
__device__ float  g_omega[R_ * R_];
__device__ float  g_cn[R_];
__device__ float  g_hs[R_];     // hs[r] = sum_{s != r} omega[r][s]

__device__ __forceinline__ void cp_async16(unsigned saddr, const void* gaddr) {
    asm volatile("cp.async.ca.shared.global [%0], [%1], 16;" :: "r"(saddr), "l"(gaddr));
}
__device__ __forceinline__ void cp_commit() {
    asm volatile("cp.async.commit_group;");
}

// ---------------------------------------------------------------------------
// Setup: 4 blocks x 256 threads; block b handles rows [8b, 8b+8).
// ---------------------------------------------------------------------------
__global__ void __launch_bounds__(256) sheaf_setup_kernel(const float* __restrict__ gc) {
    __shared__ float sc[R_][D_ + 1];
    const int tid = threadIdx.x;
    for (int i = tid; i < R_ * D_; i += 256) sc[i >> 6][i & 63] = gc[i];
    __syncthreads();
    const int r = blockIdx.x * 8 + (tid >> 5);
    const int s = tid & 31;
    float cd = 0.f;
#pragma unroll 8
    for (int d = 0; d < D_; d++) {
        float df = sc[r][d] - sc[s][d];
        cd = fmaf(df, df, cd);
    }
    float omv = expf(-cd);
    g_omega[r * R_ + s] = omv;
    float hs = omv;
#pragma unroll
    for (int off = 16; off; off >>= 1)
        hs += __shfl_xor_sync(0xffffffffu, hs, off);
    if (s == 0) g_hs[r] = hs - 1.0f;
    float t = sc[r][s] * sc[r][s] + sc[r][s + 32] * sc[r][s + 32];
#pragma unroll
    for (int off = 16; off; off >>= 1)
        t += __shfl_xor_sync(0xffffffffu, t, off);
    if (s == 1) g_cn[r] = t;
    if (r == 0 && s == 2) { g_acc = 0.0; g_done = 0u; }
}

// ---------------------------------------------------------------------------
// Fully-unrolled pair segments for warp W. Rows {W, 15-W, 16+W, 31-W} are
// sorted ascending for W in 0..7; segment membership:
//   s in (r0,r1]: row r0;  (r1,r2]: +r1;  (r2,r3]: +r2;  (r3,31]: +r3.
// All s constexpr after unroll -> immediate LDS offsets + immediate shfl.
// ---------------------------------------------------------------------------
template<int W>
__device__ __forceinline__ void pair_loop(
    int lane, const float2 (*s_pb)[R_],
    float om0, float om1, float om2, float om3,
    const float pr2x[4], const float pr2y[4], float& lacc)
{
    constexpr int r0 = W, r1 = 15 - W, r2 = 16 + W, r3 = 31 - W;
#pragma unroll
    for (int s = r0 + 1; s <= r1; s++) {
        float2 ps = s_pb[s][lane];
        float m0 = fmaf(0.5f, ps.x, pr2x[0]);
        float m1 = fmaf(0.5f, ps.y, pr2y[0]);
        float tt = fmaf(m0, __log2f(m0), m1 * __log2f(m1));
        lacc = fmaf(__shfl_sync(0xffffffffu, om0, s), tt, lacc);
    }
#pragma unroll
    for (int s = r1 + 1; s <= r2; s++) {
        float2 ps = s_pb[s][lane];
        float m0 = fmaf(0.5f, ps.x, pr2x[0]);
        float m1 = fmaf(0.5f, ps.y, pr2y[0]);
        float tt = fmaf(m0, __log2f(m0), m1 * __log2f(m1));
        lacc = fmaf(__shfl_sync(0xffffffffu, om0, s), tt, lacc);
        m0 = fmaf(0.5f, ps.x, pr2x[1]);
        m1 = fmaf(0.5f, ps.y, pr2y[1]);
        tt = fmaf(m0, __log2f(m0), m1 * __log2f(m1));
        lacc = fmaf(__shfl_sync(0xffffffffu, om1, s), tt, lacc);
    }
#pragma unroll
    for (int s = r2 + 1; s <= r3; s++) {
        float2 ps = s_pb[s][lane];
        float m0 = fmaf(0.5f, ps.x, pr2x[0]);
        float m1 = fmaf(0.5f, ps.y, pr2y[0]);
        float tt = fmaf(m0, __log2f(m0), m1 * __log2f(m1));
        lacc = fmaf(__shfl_sync(0xffffffffu, om0, s), tt, lacc);
        m0 = fmaf(0.5f, ps.x, pr2x[1]);
        m1 = fmaf(0.5f, ps.y, pr2y[1]);
        tt = fmaf(m0, __log2f(m0), m1 * __log2f(m1));
        lacc = fmaf(__shfl_sync(0xffffffffu, om1, s), tt, lacc);
        m0 = fmaf(0.5f, ps.x, pr2x[2]);
        m1 = fmaf(0.5f, ps.y, pr2y[2]);
        tt = fmaf(m0, __log2f(m0), m1 * __log2f(m1));
        lacc = fmaf(__shfl_sync(0xffffffffu, om2, s), tt, lacc);
    }
#pragma unroll
    for (int s = r3 + 1; s < R_; s++) {
        float2 ps = s_pb[s][lane];
        float m0 = fmaf(0.5f, ps.x, pr2x[0]);
        float m1 = fmaf(0.5f, ps.y, pr2y[0]);
        float tt = fmaf(m0, __log2f(m0), m1 * __log2f(m1));
        lacc = fmaf(__shfl_sync(0xffffffffu, om0, s), tt, lacc);
        m0 = fmaf(0.5f, ps.x, pr2x[1]);
        m1 = fmaf(0.5f, ps.y, pr2y[1]);
        tt = fmaf(m0, __log2f(m0), m1 * __log2f(m1));
        lacc = fmaf(__shfl_sync(0xffffffffu, om1, s), tt, lacc);
        m0 = fmaf(0.5f, ps.x, pr2x[2]);
        m1 = fmaf(0.5f, ps.y, pr2y[2]);
        tt = fmaf(m0, __log2f(m0), m1 * __log2f(m1));
        lacc = fmaf(__shfl_sync(0xffffffffu, om2, s), tt, lacc);
        m0 = fmaf(0.5f, ps.x, pr2x[3]);
        m1 = fmaf(0.5f, ps.y, pr2y[3]);
        tt = fmaf(m0, __log2f(m0), m1 * __log2f(m1));
        lacc = fmaf(__shfl_sync(0xffffffffu, om3, s), tt, lacc);
    }
}

// ---------------------------------------------------------------------------
// Main: one CTA per 2 tiles, 256 threads, 7 CTAs/SM target.
// m double-buffered; p single-buffered (prefetch overlapped with pair loop).
// ---------------------------------------------------------------------------
__global__ void __launch_bounds__(256, 7) sheaf_kernel(
    const float* __restrict__ gm,
    const float* __restrict__ gw,
    const float* __restrict__ gp,
    const float* __restrict__ gc,
    float* __restrict__ gout)
{
    __shared__ float  s_c[R_][68];        // centers row-major, 16B rows
    __shared__ float4 s_m[2][256];        // double-buffered m tile
    __shared__ float4 s_p[256];           // single-buffered p tile
    __shared__ float  s_w[2][P_];
    __shared__ float  s_sm[P_][R_ + 1];
    __shared__ float2 s_pb[R_][R_];       // [r][lane] = (p_bar[2l], p_bar[2l+1])
    __shared__ float  s_cn[R_];
    __shared__ float  s_hs[R_];
    __shared__ float  s_red[8];

    const int tid  = threadIdx.x;
    const int lane = tid & 31;
    const int wid  = tid >> 5;
    const int bt0  = blockIdx.x * TPC;

    const int r0 = wid, r1 = 15 - wid, r2 = 16 + wid, r3 = 31 - wid;

    // per-CTA constants
    for (int i = tid; i < R_ * D_; i += 256) s_c[i >> 6][i & 63] = gc[i];
    if (tid < R_) { s_cn[tid] = g_cn[tid]; s_hs[tid] = g_hs[tid]; }

    // tile-invariant omega rows, register-resident
    const float om0 = g_omega[r0 * R_ + lane];
    const float om1 = g_omega[r1 * R_ + lane];
    const float om2 = g_omega[r2 * R_ + lane];
    const float om3 = g_omega[r3 * R_ + lane];

    // prologue: async-copy m0 + p0 (group 0)
    {
        unsigned a = (unsigned)__cvta_generic_to_shared(&s_m[0][tid]);
        unsigned b = (unsigned)__cvta_generic_to_shared(&s_p[tid]);
        cp_async16(a, (const float4*)(gm + (size_t)bt0 * 1024) + tid);
        cp_async16(b, (const float4*)(gp + (size_t)bt0 * 1024) + tid);
        cp_commit();
    }
    float pw = (tid < P_) ? gw[(size_t)bt0 * P_ + tid] : 0.f;

    float lacc = 0.f;   // per-lane, log2 domain
    float eacc = 0.f;   // lane-uniform per warp, log2 domain

#pragma unroll
    for (int t = 0; t < TPC; t++) {
        if (t + 1 < TPC) {
            // prefetch m(t+1) into the other buffer
            unsigned a = (unsigned)__cvta_generic_to_shared(&s_m[t + 1][tid]);
            cp_async16(a, (const float4*)(gm + (size_t)(bt0 + t + 1) * 1024) + tid);
            cp_commit();
            asm volatile("cp.async.wait_group 1;");   // m(t), p(t) done
        } else {
            asm volatile("cp.async.wait_group 0;");   // all done
        }
        if (tid < P_) s_w[t][tid] = pw;
        __syncthreads();   // buffers visible; all warps done pair(t-1)
        if (t + 1 < TPC && tid < P_) pw = gw[(size_t)(bt0 + t + 1) * P_ + tid];

        const float* smt = (const float*)s_m[t];

        // ---- step 1: logits = 2*m.c - |c|^2 (no max-sub; |l| << 88) ----
        {
            const int p0 = wid, p1 = wid + 8;
            const int r = lane;
            float a0 = 0.f, a1 = 0.f;
#pragma unroll
            for (int d = 0; d < D_; d += 4) {
                float4 cv  = *(const float4*)&s_c[r][d];
                float4 mv0 = *(const float4*)&smt[p0 * D_ + d];
                float4 mv1 = *(const float4*)&smt[p1 * D_ + d];
                a0 = fmaf(mv0.x, cv.x, fmaf(mv0.y, cv.y, fmaf(mv0.z, cv.z, fmaf(mv0.w, cv.w, a0))));
                a1 = fmaf(mv1.x, cv.x, fmaf(mv1.y, cv.y, fmaf(mv1.z, cv.z, fmaf(mv1.w, cv.w, a1))));
            }
            const float cn = s_cn[r];
            float e0 = __expf(fmaf(2.f, a0, -cn));
            float e1 = __expf(fmaf(2.f, a1, -cn));
            float sm0 = e0, sm1 = e1;
#pragma unroll
            for (int off = 16; off; off >>= 1) {
                sm0 += __shfl_xor_sync(0xffffffffu, sm0, off);
                sm1 += __shfl_xor_sync(0xffffffffu, sm1, off);
            }
            s_sm[p0][lane] = e0 * (s_w[t][p0] / sm0);
            s_sm[p1][lane] = e1 * (s_w[t][p1] / sm1);
        }
        __syncthreads();

        // ---- step 3: p_bar + E_r; rows {r0..r3}; LDS.64 k-pairs ----
        float pr2x[4], pr2y[4];
        {
            const float* spt = (const float*)s_p;
            const int rows[4] = { r0, r1, r2, r3 };
            float acc0[4] = {0.f,0.f,0.f,0.f};
            float acc1[4] = {0.f,0.f,0.f,0.f};
#pragma unroll
            for (int pp = 0; pp < P_; pp++) {
                float2 sp = *(const float2*)&spt[pp * K_ + 2 * lane];
#pragma unroll
                for (int j = 0; j < 4; j++) {
                    float g = s_sm[pp][rows[j]];
                    acc0[j] = fmaf(sp.x, g, acc0[j]);
                    acc1[j] = fmaf(sp.y, g, acc1[j]);
                }
            }
#pragma unroll
            for (int j = 0; j < 4; j++) {
                const int r = rows[j];
                float v = (lane < P_) ? s_sm[lane][r] : 0.f;
#pragma unroll
                for (int off = 16; off; off >>= 1)
                    v += __shfl_xor_sync(0xffffffffu, v, off);
                float tm = 1.0f / (v + 1e-6f);
                float pb0 = acc0[j] * tm;
                float pb1 = acc1[j] * tm;
                s_pb[r][lane] = make_float2(pb0, pb1);
                pr2x[j] = fmaf(0.5f, pb0, 1e-8f);
                pr2y[j] = fmaf(0.5f, pb1, 1e-8f);
                float e = fmaf(pb0, __log2f(pb0 + 1e-8f), pb1 * __log2f(pb1 + 1e-8f));
#pragma unroll
                for (int off = 16; off; off >>= 1)
                    e += __shfl_xor_sync(0xffffffffu, e, off);
                eacc = fmaf(e, s_hs[r], eacc);
            }
        }
        __syncthreads();   // step3 done: s_p free for prefetch, s_pb ready

        // prefetch p(t+1) into the single buffer, overlapped with pair loop
        if (t + 1 < TPC) {
            unsigned b = (unsigned)__cvta_generic_to_shared(&s_p[tid]);
            cp_async16(b, (const float4*)(gp + (size_t)(bt0 + t + 1) * 1024) + tid);
            cp_commit();
        }

        // ---- pair loop: fully unrolled per-warp variant ----
        switch (wid) {
            case 0: pair_loop<0>(lane, s_pb, om0, om1, om2, om3, pr2x, pr2y, lacc); break;
            case 1: pair_loop<1>(lane, s_pb, om0, om1, om2, om3, pr2x, pr2y, lacc); break;
            case 2: pair_loop<2>(lane, s_pb, om0, om1, om2, om3, pr2x, pr2y, lacc); break;
            case 3: pair_loop<3>(lane, s_pb, om0, om1, om2, om3, pr2x, pr2y, lacc); break;
            case 4: pair_loop<4>(lane, s_pb, om0, om1, om2, om3, pr2x, pr2y, lacc); break;
            case 5: pair_loop<5>(lane, s_pb, om0, om1, om2, om3, pr2x, pr2y, lacc); break;
            case 6: pair_loop<6>(lane, s_pb, om0, om1, om2, om3, pr2x, pr2y, lacc); break;
            case 7: pair_loop<7>(lane, s_pb, om0, om1, om2, om3, pr2x, pr2y, lacc); break;
        }
    }

    // ---- final reduction + last-CTA writeout (log2 domain, scale once) ----
#pragma unroll
    for (int off = 16; off; off >>= 1)
        lacc += __shfl_xor_sync(0xffffffffu, lacc, off);
    if (lane == 0) s_red[wid] = fmaf(0.5f, eacc, -lacc) * LN2;
    __syncthreads();
    if (tid == 0) {
        float a = 0.f;
#pragma unroll
        for (int i = 0; i < 8; i++) a += s_red[i];
        atomicAdd(&g_acc, (double)a);
        __threadfence();
        unsigned int ticket = atomicAdd(&g_done, 1u);
        if (ticket == gridDim.x - 1) {
            double total = *(volatile double*)&g_acc;
            gout[0] = (float)(total / (496.0 + 1e-8));
        }
    }
}

extern "C" void kernel_launch(void* const* d_in, const int* in_sizes, int n_in,
                              void* d_out, int out_size) {
    const float* m = (const float*)d_in[0];
    const float* w = (const float*)d_in[1];
    const float* p = (const float*)d_in[2];
    const float* c = (const float*)d_in[3];
    float* out = (float*)d_out;
    (void)in_sizes; (void)n_in; (void)out_size;

    sheaf_setup_kernel<<<4, 256>>>(c);
    sheaf_kernel<<<BT / TPC, 256>>>(m, w, p, c, out);
}